// round 5
// baseline (speedup 1.0000x reference)
#include <cuda_runtime.h>
#include <cstdint>

#define B_  16384
#define L_  50
#define D_  128
#define TM  64          // batch rows per linear CTA

// XOR-swizzled smem index for row-major [rows][128] fp32 tile
#define SW(r, k) (((r) << 7) + ((k) ^ (((r) & 7) << 2)))

// 8 MB scratch for the pooled history embedding [B, D]
__device__ float g_his[B_ * D_];

// ---------------------------------------------------------------------------
// Kernel 1: masked gather-sum. One warp per batch row, float4 per lane.
// Measured ~5.4 TB/s effective — near random-DRAM ceiling. Unchanged.
// ---------------------------------------------------------------------------
__global__ __launch_bounds__(256) void gather_kernel(
    const int*    __restrict__ entities,
    const int*    __restrict__ history,
    const int*    __restrict__ hist_len,
    const float4* __restrict__ embv)
{
    const int warp = threadIdx.x >> 5;
    const int lane = threadIdx.x & 31;
    const int b    = (blockIdx.x << 3) + warp;

    __shared__ int sh_idx[8][52];

    const int n = hist_len[b];
    for (int l = lane; l < n; l += 32)
        sh_idx[warp][l] = history[b * L_ + l];
    __syncwarp();

    float4 a0 = make_float4(0.f, 0.f, 0.f, 0.f);
    float4 a1 = a0, a2 = a0, a3 = a0;

    int l = 0;
    for (; l + 4 <= n; l += 4) {
        const long i0 = sh_idx[warp][l + 0];
        const long i1 = sh_idx[warp][l + 1];
        const long i2 = sh_idx[warp][l + 2];
        const long i3 = sh_idx[warp][l + 3];
        float4 v0 = __ldg(&embv[i0 * 32 + lane]);
        float4 v1 = __ldg(&embv[i1 * 32 + lane]);
        float4 v2 = __ldg(&embv[i2 * 32 + lane]);
        float4 v3 = __ldg(&embv[i3 * 32 + lane]);
        a0.x += v0.x; a0.y += v0.y; a0.z += v0.z; a0.w += v0.w;
        a1.x += v1.x; a1.y += v1.y; a1.z += v1.z; a1.w += v1.w;
        a2.x += v2.x; a2.y += v2.y; a2.z += v2.z; a2.w += v2.w;
        a3.x += v3.x; a3.y += v3.y; a3.z += v3.z; a3.w += v3.w;
    }
    for (; l < n; l++) {
        const long i0 = sh_idx[warp][l];
        float4 v0 = __ldg(&embv[i0 * 32 + lane]);
        a0.x += v0.x; a0.y += v0.y; a0.z += v0.z; a0.w += v0.w;
    }

    float4 acc;
    acc.x = (a0.x + a1.x) + (a2.x + a3.x);
    acc.y = (a0.y + a1.y) + (a2.y + a3.y);
    acc.z = (a0.z + a1.z) + (a2.z + a3.z);
    acc.w = (a0.w + a1.w) + (a2.w + a3.w);

    if (n == 0)
        acc = __ldg(&embv[(long)entities[b] * 32 + lane]);

    ((float4*)g_his)[b * 32 + lane] = acc;
}

// ---------------------------------------------------------------------------
// TF32 helpers
// ---------------------------------------------------------------------------
__device__ __forceinline__ uint32_t f2tf32(float x) {
    uint32_t r;
    asm("cvt.rna.tf32.f32 %0, %1;" : "=r"(r) : "f"(x));
    return r;
}
__device__ __forceinline__ void split_tf32(float x, uint32_t& hi, uint32_t& lo) {
    hi = f2tf32(x);
    lo = f2tf32(x - __uint_as_float(hi));
}
__device__ __forceinline__ void mma_tf32(float c[4], const uint32_t a[4],
                                         uint32_t b0, uint32_t b1) {
    asm volatile(
        "mma.sync.aligned.m16n8k8.row.col.f32.tf32.tf32.f32 "
        "{%0,%1,%2,%3}, {%4,%5,%6,%7}, {%8,%9}, {%0,%1,%2,%3};"
        : "+f"(c[0]), "+f"(c[1]), "+f"(c[2]), "+f"(c[3])
        : "r"(a[0]), "r"(a[1]), "r"(a[2]), "r"(a[3]), "r"(b0), "r"(b1));
}

// ---------------------------------------------------------------------------
// Kernel 2: out = his @ W^T + bias via 3-pass split-TF32 mma.sync.
// CTA = 64x128 tile, 8 warps (warp = 16 rows x 64 cols).
// smem: his tile raw [64][128] (32KB) + W raw [128][128] (64KB), XOR-swizzled.
// hi/lo splitting done in registers at fragment load.
// ---------------------------------------------------------------------------
__global__ __launch_bounds__(256, 2) void linear_kernel(
    const float4* __restrict__ Wv,
    const float*  __restrict__ bias,
    float*        __restrict__ out)
{
    extern __shared__ float sm[];
    float* hs = sm;               // [64][128] swizzled
    float* ws = sm + TM * 128;    // [128][128] swizzled

    const int tid  = threadIdx.x;
    const int lane = tid & 31;
    const int warp = tid >> 5;
    const int gq   = lane >> 2;      // 0..7
    const int tq   = lane & 3;       // 0..3
    const int wm   = warp >> 1;      // 0..3 : 16-row group
    const int wn   = warp & 1;       // 0..1 : 64-col group
    const int row0 = blockIdx.x * TM;

    const float4* hisv = (const float4*)g_his;

    // Stage his tile (64 rows) and raw W (128 rows), both swizzled.
    for (int t = tid; t < TM * 32; t += 256) {
        const int r  = t >> 5;
        const int kv = t & 31;
        float4 v = hisv[(long)(row0 + r) * 32 + kv];
        *(float4*)&hs[SW(r, kv * 4)] = v;
    }
    for (int t = tid; t < 128 * 32; t += 256) {
        const int r  = t >> 5;
        const int kv = t & 31;
        float4 w = Wv[(long)r * 32 + kv];
        *(float4*)&ws[SW(r, kv * 4)] = w;
    }
    __syncthreads();

    // Accumulators initialized with bias.
    float c[8][4];
#pragma unroll
    for (int n = 0; n < 8; n++) {
        const int col = wn * 64 + n * 8 + 2 * tq;
        const float b0 = __ldg(&bias[col]);
        const float b1 = __ldg(&bias[col + 1]);
        c[n][0] = b0; c[n][1] = b1;
        c[n][2] = b0; c[n][3] = b1;
    }

#pragma unroll
    for (int kt = 0; kt < 16; kt++) {
        const int k0 = kt * 8;

        // A fragment (16 rows x 8 k), split hi/lo in registers.
        uint32_t ahi[4], alo[4];
        {
            const int r = wm * 16 + gq;
            float x0 = hs[SW(r,     k0 + tq)];
            float x1 = hs[SW(r + 8, k0 + tq)];
            float x2 = hs[SW(r,     k0 + tq + 4)];
            float x3 = hs[SW(r + 8, k0 + tq + 4)];
            split_tf32(x0, ahi[0], alo[0]);
            split_tf32(x1, ahi[1], alo[1]);
            split_tf32(x2, ahi[2], alo[2]);
            split_tf32(x3, ahi[3], alo[3]);
        }

#pragma unroll
        for (int n = 0; n < 8; n++) {
            const int j = wn * 64 + n * 8 + gq;   // output col = W row
            float w0 = ws[SW(j, k0 + tq)];
            float w1 = ws[SW(j, k0 + tq + 4)];
            uint32_t bh0, bl0, bh1, bl1;
            split_tf32(w0, bh0, bl0);
            split_tf32(w1, bh1, bl1);
            mma_tf32(c[n], ahi, bh0, bh1);   // Ah*Bh
            mma_tf32(c[n], ahi, bl0, bl1);   // Ah*Bl
            mma_tf32(c[n], alo, bh0, bh1);   // Al*Bh
        }
    }

    // Epilogue
#pragma unroll
    for (int n = 0; n < 8; n++) {
        const int r   = row0 + wm * 16 + gq;
        const int col = wn * 64 + n * 8 + 2 * tq;
        *(float2*)&out[(long)r * 128 + col]       = make_float2(c[n][0], c[n][1]);
        *(float2*)&out[(long)(r + 8) * 128 + col] = make_float2(c[n][2], c[n][3]);
    }
}

// ---------------------------------------------------------------------------
extern "C" void kernel_launch(void* const* d_in, const int* in_sizes, int n_in,
                              void* d_out, int out_size)
{
    const int*   entities = (const int*)d_in[0];
    const int*   history  = (const int*)d_in[1];
    const int*   hist_len = (const int*)d_in[2];
    const float* emb      = (const float*)d_in[3];
    const float* W        = (const float*)d_in[4];
    const float* bias     = (const float*)d_in[5];
    float*       out      = (float*)d_out;

    gather_kernel<<<B_ / 8, 256>>>(entities, history, hist_len,
                                   (const float4*)emb);

    const size_t smem = (size_t)(TM * 128 + 128 * 128) * sizeof(float); // 96KB
    cudaFuncSetAttribute(linear_kernel,
                         cudaFuncAttributeMaxDynamicSharedMemorySize,
                         (int)smem);
    linear_kernel<<<B_ / TM, 256, smem>>>((const float4*)W, bias, out);
}